// round 14
// baseline (speedup 1.0000x reference)
#include <cuda_runtime.h>
#include <cuda_fp16.h>
#include <cstdint>

// Problem constants
#define NTOK 32768
#define KC   1024
#define DD   256
#define KA   512            // stored split length per matrix: [hi | lo]
#define TINV 10.0f

// Output layout (flattened tuple order)
static const long OFF_ZQ    = 0;
static const long OFF_CODES = 8388608;
static const long OFF_LOSS  = 8421376;
static const long OFF_PERP  = 8421377;
static const long OFF_ENT   = 8421378;
static const long OFF_SOFT  = 8421379;   // only 4B-aligned -> scalar access only
static const long OFF_NEMB  = 41975811;
static const long OFF_NCS   = 42237955;
static const long OFF_NEA   = 42238979;

// Device scratch
__device__ float  g_e2[KC];
__device__ float  g_counts[KC];
__device__ float  g_esum[KC * DD];
__device__ float  g_csn[KC];
__device__ float  g_loss;
__device__ __half g_A[(size_t)NTOK * KA];   // [z_hi | z_lo]
__device__ __half g_B[(size_t)KC   * KA];   // [e_hi | e_lo]

// ---------------------------------------------------------------------------
__device__ __forceinline__ uint32_t smem_u32(const void* p) {
    uint32_t a;
    asm("{ .reg .u64 t; cvta.to.shared.u64 t, %1; cvt.u32.u64 %0, t; }"
        : "=r"(a) : "l"(p));
    return a;
}
#define SWZ(off) ((off) ^ (((off) >> 3) & 0x70))

__device__ __forceinline__ void cp16(uint32_t s, const void* g) {
    asm volatile("cp.async.cg.shared.global [%0], [%1], 16;"
                 :: "r"(s), "l"(g) : "memory");
}

#define LDSM4(r, addr) \
    asm volatile("ldmatrix.sync.aligned.m8n8.x4.shared.b16 {%0,%1,%2,%3}, [%4];" \
        : "=r"((r)[0]), "=r"((r)[1]), "=r"((r)[2]), "=r"((r)[3]) : "r"(addr))

#define MMA16816(c, a, b) \
    asm volatile("mma.sync.aligned.m16n8k16.row.col.f32.f16.f16.f32 " \
        "{%0,%1,%2,%3}, {%4,%5,%6,%7}, {%8,%9}, {%0,%1,%2,%3};" \
        : "+f"((c)[0]), "+f"((c)[1]), "+f"((c)[2]), "+f"((c)[3]) \
        : "r"((a)[0]), "r"((a)[1]), "r"((a)[2]), "r"((a)[3]), \
          "r"((b)[0]), "r"((b)[1]))

__device__ __forceinline__ void red4(float* a, float4 v) {
    asm volatile("red.global.add.v4.f32 [%0], {%1,%2,%3,%4};"
                 :: "l"(a), "f"(v.x), "f"(v.y), "f"(v.z), "f"(v.w) : "memory");
}

// ---------------------------------------------------------------------------
// Fused producer: conv_z over the whole grid; blocks < 256 additionally do
// scratch zeroing, embed conversion into g_B, and e2.
__global__ __launch_bounds__(256)
void prep_k(const float* __restrict__ z, const float* __restrict__ embed) {
    int t = blockIdx.x * 256 + threadIdx.x;     // 0 .. 2^21-1 (float4 index)

    // conv_z: one float4 of z per thread -> g_A [hi | lo]
    {
        int n = t >> 6, d4 = (t & 63) * 4;
        float4 v = ((const float4*)z)[t];
        __half hx = __float2half(v.x), hy = __float2half(v.y);
        __half hz = __float2half(v.z), hw = __float2half(v.w);
        __half lx = __float2half(v.x - __half2float(hx));
        __half ly = __float2half(v.y - __half2float(hy));
        __half lz = __float2half(v.z - __half2float(hz));
        __half lw = __float2half(v.w - __half2float(hw));
        __half* r = g_A + (size_t)n * KA;
        *(__half2*)(r + d4)           = __halves2half2(hx, hy);
        *(__half2*)(r + d4 + 2)       = __halves2half2(hz, hw);
        *(__half2*)(r + 256 + d4)     = __halves2half2(lx, ly);
        *(__half2*)(r + 256 + d4 + 2) = __halves2half2(lz, lw);
    }

    if (blockIdx.x >= 256) return;
    // t now in [0, 65536): embed-side work

#pragma unroll
    for (int j = 0; j < 4; j++) g_esum[t * 4 + j] = 0.0f;
    if (t < KC)  g_counts[t] = 0.0f;
    if (t == 0)  g_loss = 0.0f;

    {
        int n = t >> 6, d4 = (t & 63) * 4;
        float4 v = ((const float4*)embed)[t];
        __half hx = __float2half(v.x), hy = __float2half(v.y);
        __half hz = __float2half(v.z), hw = __float2half(v.w);
        __half lx = __float2half(v.x - __half2float(hx));
        __half ly = __float2half(v.y - __half2float(hy));
        __half lz = __float2half(v.z - __half2float(hz));
        __half lw = __float2half(v.w - __half2float(hw));
        __half* r = g_B + (size_t)n * KA;
        *(__half2*)(r + d4)           = __halves2half2(hx, hy);
        *(__half2*)(r + d4 + 2)       = __halves2half2(hz, hw);
        *(__half2*)(r + 256 + d4)     = __halves2half2(lx, ly);
        *(__half2*)(r + 256 + d4 + 2) = __halves2half2(lz, lw);
    }

    // e2: one warp per code row (warps 0..1023 of this sub-range)
    int w = t >> 5, lane = t & 31;
    if (w < KC) {
        const float4* row = (const float4*)(embed + (size_t)w * DD);
        float s = 0.0f;
#pragma unroll
        for (int j = 0; j < 2; j++) {
            float4 v = row[lane + 32 * j];
            s += v.x * v.x + v.y * v.y + v.z * v.z + v.w * v.w;
        }
#pragma unroll
        for (int o = 16; o; o >>= 1) s += __shfl_xor_sync(0xffffffffu, s, o);
        if (lane == 0) g_e2[w] = s;
    }
}

// ---------------------------------------------------------------------------
// HMMA GEMM (frozen geometry): CTA = 128 tokens x 128 codes, 8 warps as
// 4(m) x 2(n), warp tile 32x64, 3-stage cp.async pipeline, 2 CTAs/SM.
// Logical K=768 as 12 chunks of 64 remapped into [hi|lo] K=512 buffers:
//   c 0-3: A hi x B hi; c 4-7: A lo x B hi; c 8-11: A hi x B lo.
// Writes dist = e2 - 2*dot into the soft region (scratch).
#define SM_STG 32768     // per stage: A 16KB + B 16KB
#define SM_TOT (3 * SM_STG)
#define NCH    12

__device__ __forceinline__ void load_chunk(uint32_t sb, const char* Ag,
                                           const char* Bg, int c, int stg,
                                           int tid) {
    int ac = (c < 8) ? c : c - 8;
    int bc = (c < 4) ? c : c - 4;
    uint32_t base = sb + stg * SM_STG;
#pragma unroll
    for (int q = 0; q < 4; q++) {              // A: 128 rows x 128B
        int i = tid + 256 * q, r = i >> 3, j = i & 7;
        uint32_t off = (uint32_t)(r * 128 + j * 16);
        cp16(base + SWZ(off), Ag + (size_t)r * (KA * 2) + ac * 128 + j * 16);
    }
#pragma unroll
    for (int q = 0; q < 4; q++) {              // B: 128 rows x 128B
        int i = tid + 256 * q, r = i >> 3, j = i & 7;
        uint32_t off = (uint32_t)(r * 128 + j * 16);
        cp16(base + 16384 + SWZ(off), Bg + (size_t)r * (KA * 2) + bc * 128 + j * 16);
    }
    asm volatile("cp.async.commit_group;" ::: "memory");
}

extern __shared__ char gsm[];

__global__ __launch_bounds__(256, 2)
void vq_gemm(float* __restrict__ out) {
    __shared__ float e2t[128];
    uint32_t sb = smem_u32(gsm);
    int tid = threadIdx.x, lane = tid & 31, wid = tid >> 5;
    int row0 = blockIdx.x * 128, col0 = blockIdx.y * 128;
    int wm = (wid & 3) * 32, wn = (wid >> 2) * 64;

    if (tid < 128) e2t[tid] = g_e2[col0 + tid];

    const char* Ag = (const char*)g_A + (size_t)row0 * (KA * 2);
    const char* Bg = (const char*)g_B + (size_t)col0 * (KA * 2);

    float acc[2][8][4] = {};

    load_chunk(sb, Ag, Bg, 0, 0, tid);
    load_chunk(sb, Ag, Bg, 1, 1, tid);

    int stg = 0, lstg = 2;
    for (int c = 0; c < NCH; c++) {
        if (c < NCH - 1) asm volatile("cp.async.wait_group 1;" ::: "memory");
        else             asm volatile("cp.async.wait_group 0;" ::: "memory");
        __syncthreads();
        if (c + 2 < NCH) load_chunk(sb, Ag, Bg, c + 2, lstg, tid);

        uint32_t sa = sb + stg * SM_STG;
        uint32_t sB = sa + 16384;
#pragma unroll
        for (int ks = 0; ks < 4; ks++) {
            uint32_t a[2][4];
#pragma unroll
            for (int mt = 0; mt < 2; mt++) {
                uint32_t off = (uint32_t)((wm + mt * 16 + (lane & 15)) * 128
                                          + ks * 32 + (lane >> 4) * 16);
                LDSM4(a[mt], sa + SWZ(off));
            }
            uint32_t b[8][2];
#pragma unroll
            for (int p = 0; p < 4; p++) {
                uint32_t r4[4];
                uint32_t off = (uint32_t)((wn + p * 16 + (lane & 7)
                                           + ((lane >> 4) << 3)) * 128
                                          + ks * 32 + ((lane >> 3) & 1) * 16);
                LDSM4(r4, sB + SWZ(off));
                b[2 * p][0] = r4[0];     b[2 * p][1] = r4[1];
                b[2 * p + 1][0] = r4[2]; b[2 * p + 1][1] = r4[3];
            }
#pragma unroll
            for (int mt = 0; mt < 2; mt++)
#pragma unroll
                for (int nt = 0; nt < 8; nt++)
                    MMA16816(acc[mt][nt], a[mt], b[nt]);
        }
        stg  = (stg  == 2) ? 0 : stg + 1;
        lstg = (lstg == 2) ? 0 : lstg + 1;
    }

    // Epilogue: dist = e2 - 2*dot, scalar stores (region only 4B-aligned).
#pragma unroll
    for (int mt = 0; mt < 2; mt++) {
#pragma unroll
        for (int nt = 0; nt < 8; nt++) {
            int r  = row0 + wm + mt * 16 + (lane >> 2);
            int lc = wn + nt * 8 + (lane & 3) * 2;
            float* d0 = out + OFF_SOFT + (size_t)r * KC + col0 + lc;
            d0[0]          = e2t[lc]     - 2.0f * acc[mt][nt][0];
            d0[1]          = e2t[lc + 1] - 2.0f * acc[mt][nt][1];
            d0[8 * KC]     = e2t[lc]     - 2.0f * acc[mt][nt][2];
            d0[8 * KC + 1] = e2t[lc + 1] - 2.0f * acc[mt][nt][3];
        }
    }
}

// ---------------------------------------------------------------------------
// Per-row epilogue v2: TWO warps per row (512 codes each) -> dv[16], ~38 regs,
// higher occupancy and more outstanding loads. smem combine of (min,arg,sum).
// Block = 256 thr = 4 rows x 2 warps.
__global__ __launch_bounds__(256)
void vq_epi(const float* __restrict__ z,
            const float* __restrict__ embed,
            float* __restrict__ out) {
    __shared__ float s_mn[4][2];
    __shared__ int   s_arg[4][2];
    __shared__ float s_sum[4][2];

    int tid = threadIdx.x, lane = tid & 31, w = tid >> 5;
    int r = w >> 1, half = w & 1;
    int row = blockIdx.x * 4 + r;
    float* dist = out + OFF_SOFT + (size_t)row * KC;
    int base = half * 512;

    float dv[16];
    float mn = 3.4e38f; int arg = 0;
#pragma unroll
    for (int j = 0; j < 16; j++) {
        int k = base + j * 32 + lane;
        float d = dist[k];
        dv[j] = d;
        if (d < mn) { mn = d; arg = k; }
    }
#pragma unroll
    for (int o = 16; o; o >>= 1) {
        float ov = __shfl_xor_sync(0xffffffffu, mn, o);
        int   oa = __shfl_xor_sync(0xffffffffu, arg, o);
        if (ov < mn || (ov == mn && oa < arg)) { mn = ov; arg = oa; }
    }
    if (lane == 0) { s_mn[r][half] = mn; s_arg[r][half] = arg; }
    __syncthreads();
    {
        float m0 = s_mn[r][0], m1 = s_mn[r][1];
        int   a0 = s_arg[r][0], a1 = s_arg[r][1];
        // global min with smallest-index tie-break (a0 < a1 always holds
        // across halves, so on equal mins pick half 0)
        if (m1 < m0) { mn = m1; arg = a1; } else { mn = m0; arg = a0; }
    }

    float sum = 0.0f;
#pragma unroll
    for (int j = 0; j < 16; j++) {
        float v = __expf((mn - dv[j]) * TINV);
        dv[j] = v;
        sum += v;
    }
#pragma unroll
    for (int o = 16; o; o >>= 1) sum += __shfl_xor_sync(0xffffffffu, sum, o);
    if (lane == 0) s_sum[r][half] = sum;
    __syncthreads();
    float inv = 1.0f / (s_sum[r][0] + s_sum[r][1]);

#pragma unroll
    for (int j = 0; j < 16; j++)
        dist[base + j * 32 + lane] = dv[j] * inv;

    // z_q, loss, EMA — one float4 per lane (64 lanes cover the row)
    int code = arg;
    const float4* er4 = (const float4*)(embed + (size_t)code * DD);
    const float4* zr4 = (const float4*)(z     + (size_t)row  * DD);
    float4*       zq4 = (float4*)(out + OFF_ZQ + (size_t)row * DD);
    int i = half * 32 + lane;                  // float4 index 0..63
    float4 ev = er4[i], zv = zr4[i];
    zq4[i] = ev;
    float dx = zv.x - ev.x, dy = zv.y - ev.y;
    float dz = zv.z - ev.z, dw = zv.w - ev.w;
    float lp = dx * dx + dy * dy + dz * dz + dw * dw;
    red4(g_esum + code * DD + i * 4, zv);
#pragma unroll
    for (int o = 16; o; o >>= 1) lp += __shfl_xor_sync(0xffffffffu, lp, o);
    if (lane == 0) {
        atomicAdd(&g_loss, lp);
        if (half == 0) {
            out[OFF_CODES + row] = (float)code;
            atomicAdd(&g_counts[code], 1.0f);
        }
    }
}

// ---------------------------------------------------------------------------
__global__ void fin1(const float* __restrict__ cs, float* __restrict__ out) {
    __shared__ float part[32];
    __shared__ float bc[2];
    int k = threadIdx.x, lane = k & 31, w = k >> 5;

    float cnt = g_counts[k];
    float ncs = 0.99f * cs[k] + 0.01f * cnt;
    out[OFF_NCS + k] = ncs;

    float p = cnt * (1.0f / 32768.0f);
    float s1 = ncs;
    float s2 = -p * logf(p + 1e-10f);
#pragma unroll
    for (int o = 16; o; o >>= 1) {
        s1 += __shfl_xor_sync(0xffffffffu, s1, o);
        s2 += __shfl_xor_sync(0xffffffffu, s2, o);
    }
    if (lane == 0) part[w] = s1;
    __syncthreads();
    if (w == 0) {
        float v = part[lane];
#pragma unroll
        for (int o = 16; o; o >>= 1) v += __shfl_xor_sync(0xffffffffu, v, o);
        if (lane == 0) bc[0] = v;
    }
    __syncthreads();
    float n = bc[0];
    g_csn[k] = (ncs + 1e-5f) / (n + 1024.0f * 1e-5f) * n;

    if (lane == 0) part[w] = s2;
    __syncthreads();
    if (k == 0) {
        float ent = 0.0f;
#pragma unroll
        for (int j = 0; j < 32; j++) ent += part[j];
        out[OFF_ENT]  = ent;
        out[OFF_PERP] = expf(ent);
        out[OFF_LOSS] = g_loss * (1.0f / (32768.0f * 256.0f));
    }
}

__global__ void fin2(const float* __restrict__ ea, float* __restrict__ out) {
    int idx = blockIdx.x * 256 + threadIdx.x;
    float v = 0.99f * ea[idx] + 0.01f * g_esum[idx];
    out[OFF_NEA  + idx] = v;
    out[OFF_NEMB + idx] = v / g_csn[idx >> 8];
}

// ---------------------------------------------------------------------------
extern "C" void kernel_launch(void* const* d_in, const int* in_sizes, int n_in,
                              void* d_out, int out_size) {
    const float* z     = (const float*)d_in[0];
    const float* embed = (const float*)d_in[1];
    const float* cs    = (const float*)d_in[2];
    const float* ea    = (const float*)d_in[3];
    float* out = (float*)d_out;

    cudaFuncSetAttribute(vq_gemm, cudaFuncAttributeMaxDynamicSharedMemorySize,
                         SM_TOT);

    prep_k<<<8192, 256>>>(z, embed);
    vq_gemm<<<dim3(256, 8), 256, SM_TOT>>>(out);
    vq_epi<<<8192, 256>>>(z, embed, out);
    fin1<<<1, 1024>>>(cs, out);
    fin2<<<1024, 256>>>(ea, out);
}

// round 15
// speedup vs baseline: 1.3454x; 1.3454x over previous
#include <cuda_runtime.h>
#include <cuda_fp16.h>
#include <cstdint>

// Problem constants
#define NTOK 32768
#define KC   1024
#define DD   256
#define KA   512            // stored split length per matrix: [hi | lo]
#define TINV 10.0f

// Output layout (flattened tuple order)
static const long OFF_ZQ    = 0;
static const long OFF_CODES = 8388608;
static const long OFF_LOSS  = 8421376;
static const long OFF_PERP  = 8421377;
static const long OFF_ENT   = 8421378;
static const long OFF_SOFT  = 8421379;   // only 4B-aligned -> scalar access only
static const long OFF_NEMB  = 41975811;
static const long OFF_NCS   = 42237955;
static const long OFF_NEA   = 42238979;

// Device scratch
__device__ float  g_e2[KC];
__device__ float  g_counts[KC];
__device__ float  g_esum[KC * DD];
__device__ float  g_csn[KC];
__device__ float  g_loss;
__device__ __half g_A[(size_t)NTOK * KA];        // [z_hi | z_lo]
__device__ __half g_B[(size_t)KC   * KA];        // [e_hi | e_lo]
__device__ float4 g_dist4[(size_t)NTOK * KC / 4]; // 16B-aligned dist scratch

// ---------------------------------------------------------------------------
__device__ __forceinline__ uint32_t smem_u32(const void* p) {
    uint32_t a;
    asm("{ .reg .u64 t; cvta.to.shared.u64 t, %1; cvt.u32.u64 %0, t; }"
        : "=r"(a) : "l"(p));
    return a;
}
#define SWZ(off) ((off) ^ (((off) >> 3) & 0x70))

__device__ __forceinline__ void cp16(uint32_t s, const void* g) {
    asm volatile("cp.async.cg.shared.global [%0], [%1], 16;"
                 :: "r"(s), "l"(g) : "memory");
}

#define LDSM4(r, addr) \
    asm volatile("ldmatrix.sync.aligned.m8n8.x4.shared.b16 {%0,%1,%2,%3}, [%4];" \
        : "=r"((r)[0]), "=r"((r)[1]), "=r"((r)[2]), "=r"((r)[3]) : "r"(addr))

#define MMA16816(c, a, b) \
    asm volatile("mma.sync.aligned.m16n8k16.row.col.f32.f16.f16.f32 " \
        "{%0,%1,%2,%3}, {%4,%5,%6,%7}, {%8,%9}, {%0,%1,%2,%3};" \
        : "+f"((c)[0]), "+f"((c)[1]), "+f"((c)[2]), "+f"((c)[3]) \
        : "r"((a)[0]), "r"((a)[1]), "r"((a)[2]), "r"((a)[3]), \
          "r"((b)[0]), "r"((b)[1]))

__device__ __forceinline__ void red4(float* a, float4 v) {
    asm volatile("red.global.add.v4.f32 [%0], {%1,%2,%3,%4};"
                 :: "l"(a), "f"(v.x), "f"(v.y), "f"(v.z), "f"(v.w) : "memory");
}

// ---------------------------------------------------------------------------
// Fused: zero scratch + e2[k] + conv of embed into g_B [hi|lo].
__global__ void e2zc_k(const float* __restrict__ embed) {
    int t = blockIdx.x * 256 + threadIdx.x;     // 65536 threads
#pragma unroll
    for (int j = 0; j < 4; j++) g_esum[t * 4 + j] = 0.0f;
    if (t < KC) g_counts[t] = 0.0f;
    if (t == 0) g_loss = 0.0f;

    {
        int n = t >> 6, d4 = (t & 63) * 4;
        float4 v = ((const float4*)embed)[t];
        __half hx = __float2half(v.x), hy = __float2half(v.y);
        __half hz = __float2half(v.z), hw = __float2half(v.w);
        __half lx = __float2half(v.x - __half2float(hx));
        __half ly = __float2half(v.y - __half2float(hy));
        __half lz = __float2half(v.z - __half2float(hz));
        __half lw = __float2half(v.w - __half2float(hw));
        __half* r = g_B + (size_t)n * KA;
        *(__half2*)(r + d4)           = __halves2half2(hx, hy);
        *(__half2*)(r + d4 + 2)       = __halves2half2(hz, hw);
        *(__half2*)(r + 256 + d4)     = __halves2half2(lx, ly);
        *(__half2*)(r + 256 + d4 + 2) = __halves2half2(lz, lw);
    }

    int w = t >> 5, lane = t & 31;
    if (w < KC) {
        const float4* row = (const float4*)(embed + (size_t)w * DD);
        float s = 0.0f;
#pragma unroll
        for (int j = 0; j < 2; j++) {
            float4 v = row[lane + 32 * j];
            s += v.x * v.x + v.y * v.y + v.z * v.z + v.w * v.w;
        }
#pragma unroll
        for (int o = 16; o; o >>= 1) s += __shfl_xor_sync(0xffffffffu, s, o);
        if (lane == 0) g_e2[w] = s;
    }
}

// split f32 -> (hi, lo) f16; layout [hi | lo], row length KA=512
__global__ void conv_z(const float* __restrict__ z) {
    int idx = blockIdx.x * 256 + threadIdx.x;
    int n = idx >> 6, d4 = (idx & 63) * 4;
    float4 v = ((const float4*)z)[idx];
    __half hx = __float2half(v.x), hy = __float2half(v.y);
    __half hz = __float2half(v.z), hw = __float2half(v.w);
    __half lx = __float2half(v.x - __half2float(hx));
    __half ly = __float2half(v.y - __half2float(hy));
    __half lz = __float2half(v.z - __half2float(hz));
    __half lw = __float2half(v.w - __half2float(hw));
    __half* r = g_A + (size_t)n * KA;
    *(__half2*)(r + d4)           = __halves2half2(hx, hy);
    *(__half2*)(r + d4 + 2)       = __halves2half2(hz, hw);
    *(__half2*)(r + 256 + d4)     = __halves2half2(lx, ly);
    *(__half2*)(r + 256 + d4 + 2) = __halves2half2(lz, lw);
}

// ---------------------------------------------------------------------------
// HMMA GEMM (frozen geometry): CTA = 128 tokens x 128 codes, 8 warps as
// 4(m) x 2(n), warp tile 32x64, 3-stage cp.async pipeline, 2 CTAs/SM.
// Logical K=768 as 12 chunks of 64 remapped into [hi|lo] K=512 buffers:
//   c 0-3: A hi x B hi; c 4-7: A lo x B hi; c 8-11: A hi x B lo.
// Writes dist = e2 - 2*dot into g_dist (aligned scratch) with float2 stores.
#define SM_STG 32768     // per stage: A 16KB + B 16KB
#define SM_TOT (3 * SM_STG)
#define NCH    12

__device__ __forceinline__ void load_chunk(uint32_t sb, const char* Ag,
                                           const char* Bg, int c, int stg,
                                           int tid) {
    int ac = (c < 8) ? c : c - 8;
    int bc = (c < 4) ? c : c - 4;
    uint32_t base = sb + stg * SM_STG;
#pragma unroll
    for (int q = 0; q < 4; q++) {              // A: 128 rows x 128B
        int i = tid + 256 * q, r = i >> 3, j = i & 7;
        uint32_t off = (uint32_t)(r * 128 + j * 16);
        cp16(base + SWZ(off), Ag + (size_t)r * (KA * 2) + ac * 128 + j * 16);
    }
#pragma unroll
    for (int q = 0; q < 4; q++) {              // B: 128 rows x 128B
        int i = tid + 256 * q, r = i >> 3, j = i & 7;
        uint32_t off = (uint32_t)(r * 128 + j * 16);
        cp16(base + 16384 + SWZ(off), Bg + (size_t)r * (KA * 2) + bc * 128 + j * 16);
    }
    asm volatile("cp.async.commit_group;" ::: "memory");
}

extern __shared__ char gsm[];

__global__ __launch_bounds__(256, 2)
void vq_gemm() {
    __shared__ float e2t[128];
    uint32_t sb = smem_u32(gsm);
    int tid = threadIdx.x, lane = tid & 31, wid = tid >> 5;
    int row0 = blockIdx.x * 128, col0 = blockIdx.y * 128;
    int wm = (wid & 3) * 32, wn = (wid >> 2) * 64;

    if (tid < 128) e2t[tid] = g_e2[col0 + tid];

    const char* Ag = (const char*)g_A + (size_t)row0 * (KA * 2);
    const char* Bg = (const char*)g_B + (size_t)col0 * (KA * 2);

    float acc[2][8][4] = {};

    load_chunk(sb, Ag, Bg, 0, 0, tid);
    load_chunk(sb, Ag, Bg, 1, 1, tid);

    int stg = 0, lstg = 2;
    for (int c = 0; c < NCH; c++) {
        if (c < NCH - 1) asm volatile("cp.async.wait_group 1;" ::: "memory");
        else             asm volatile("cp.async.wait_group 0;" ::: "memory");
        __syncthreads();
        if (c + 2 < NCH) load_chunk(sb, Ag, Bg, c + 2, lstg, tid);

        uint32_t sa = sb + stg * SM_STG;
        uint32_t sB = sa + 16384;
#pragma unroll
        for (int ks = 0; ks < 4; ks++) {
            uint32_t a[2][4];
#pragma unroll
            for (int mt = 0; mt < 2; mt++) {
                uint32_t off = (uint32_t)((wm + mt * 16 + (lane & 15)) * 128
                                          + ks * 32 + (lane >> 4) * 16);
                LDSM4(a[mt], sa + SWZ(off));
            }
            uint32_t b[8][2];
#pragma unroll
            for (int p = 0; p < 4; p++) {
                uint32_t r4[4];
                uint32_t off = (uint32_t)((wn + p * 16 + (lane & 7)
                                           + ((lane >> 4) << 3)) * 128
                                          + ks * 32 + ((lane >> 3) & 1) * 16);
                LDSM4(r4, sB + SWZ(off));
                b[2 * p][0] = r4[0];     b[2 * p][1] = r4[1];
                b[2 * p + 1][0] = r4[2]; b[2 * p + 1][1] = r4[3];
            }
#pragma unroll
            for (int mt = 0; mt < 2; mt++)
#pragma unroll
                for (int nt = 0; nt < 8; nt++)
                    MMA16816(acc[mt][nt], a[mt], b[nt]);
        }
        stg  = (stg  == 2) ? 0 : stg + 1;
        lstg = (lstg == 2) ? 0 : lstg + 1;
    }

    // Epilogue: dist = e2 - 2*dot into aligned scratch, float2 stores.
    float* gd = (float*)g_dist4;
#pragma unroll
    for (int mt = 0; mt < 2; mt++) {
#pragma unroll
        for (int nt = 0; nt < 8; nt++) {
            int r  = row0 + wm + mt * 16 + (lane >> 2);
            int lc = wn + nt * 8 + (lane & 3) * 2;
            float* d0 = gd + (size_t)r * KC + col0 + lc;
            float2 v0, v1;
            v0.x = e2t[lc]     - 2.0f * acc[mt][nt][0];
            v0.y = e2t[lc + 1] - 2.0f * acc[mt][nt][1];
            v1.x = e2t[lc]     - 2.0f * acc[mt][nt][2];
            v1.y = e2t[lc + 1] - 2.0f * acc[mt][nt][3];
            *(float2*)d0            = v0;
            *(float2*)(d0 + 8 * KC) = v1;
        }
    }
}

// ---------------------------------------------------------------------------
// Per-row epilogue (round-8 shape, vectorized dist loads): one warp per row,
// 8 rows per 256-thr CTA. Reads dist from g_dist4 via LDG.128, writes softmax
// to the (misaligned) soft region with coalesced scalar stores.
__global__ __launch_bounds__(256)
void vq_epi(const float* __restrict__ z,
            const float* __restrict__ embed,
            float* __restrict__ out) {
    int tid = threadIdx.x, lane = tid & 31, w = tid >> 5;
    int row = blockIdx.x * 8 + w;
    const float4* dist4 = g_dist4 + (size_t)row * (KC / 4);

    float4 dv[8];
    float mn = 3.4e38f; int arg = 0;
#pragma unroll
    for (int j = 0; j < 8; j++) {
        float4 d = dist4[j * 32 + lane];
        int k = (j * 32 + lane) * 4;
        dv[j] = d;
        if (d.x < mn) { mn = d.x; arg = k; }
        if (d.y < mn) { mn = d.y; arg = k + 1; }
        if (d.z < mn) { mn = d.z; arg = k + 2; }
        if (d.w < mn) { mn = d.w; arg = k + 3; }
    }
#pragma unroll
    for (int o = 16; o; o >>= 1) {
        float ov = __shfl_xor_sync(0xffffffffu, mn, o);
        int   oa = __shfl_xor_sync(0xffffffffu, arg, o);
        if (ov < mn || (ov == mn && oa < arg)) { mn = ov; arg = oa; }
    }

    float sum = 0.0f;
#pragma unroll
    for (int j = 0; j < 8; j++) {
        dv[j].x = __expf((mn - dv[j].x) * TINV);
        dv[j].y = __expf((mn - dv[j].y) * TINV);
        dv[j].z = __expf((mn - dv[j].z) * TINV);
        dv[j].w = __expf((mn - dv[j].w) * TINV);
        sum += dv[j].x + dv[j].y + dv[j].z + dv[j].w;
    }
#pragma unroll
    for (int o = 16; o; o >>= 1) sum += __shfl_xor_sync(0xffffffffu, sum, o);
    float inv = 1.0f / sum;

    float* soft = out + OFF_SOFT + (size_t)row * KC;
#pragma unroll
    for (int j = 0; j < 8; j++) {
        int k = (j * 32 + lane) * 4;
        soft[k]     = dv[j].x * inv;
        soft[k + 1] = dv[j].y * inv;
        soft[k + 2] = dv[j].z * inv;
        soft[k + 3] = dv[j].w * inv;
    }

    // z_q, loss, EMA — vectorized float4 + v4 reductions
    int code = arg;
    const float4* er4 = (const float4*)(embed + (size_t)code * DD);
    const float4* zr4 = (const float4*)(z     + (size_t)row  * DD);
    float4*       zq4 = (float4*)(out + OFF_ZQ + (size_t)row * DD);
    float lp = 0.0f;
#pragma unroll
    for (int j = 0; j < 2; j++) {
        int i = lane * 2 + j;                  // float4 index 0..63
        float4 ev = er4[i], zv = zr4[i];
        zq4[i] = ev;
        float dx = zv.x - ev.x, dy = zv.y - ev.y;
        float dz = zv.z - ev.z, dw = zv.w - ev.w;
        lp += dx * dx + dy * dy + dz * dz + dw * dw;
        red4(g_esum + code * DD + i * 4, zv);
    }
#pragma unroll
    for (int o = 16; o; o >>= 1) lp += __shfl_xor_sync(0xffffffffu, lp, o);
    if (lane == 0) {
        out[OFF_CODES + row] = (float)code;
        atomicAdd(&g_counts[code], 1.0f);
        atomicAdd(&g_loss, lp);
    }
}

// ---------------------------------------------------------------------------
__global__ void fin1(const float* __restrict__ cs, float* __restrict__ out) {
    __shared__ float part[32];
    __shared__ float bc[2];
    int k = threadIdx.x, lane = k & 31, w = k >> 5;

    float cnt = g_counts[k];
    float ncs = 0.99f * cs[k] + 0.01f * cnt;
    out[OFF_NCS + k] = ncs;

    float p = cnt * (1.0f / 32768.0f);
    float s1 = ncs;
    float s2 = -p * logf(p + 1e-10f);
#pragma unroll
    for (int o = 16; o; o >>= 1) {
        s1 += __shfl_xor_sync(0xffffffffu, s1, o);
        s2 += __shfl_xor_sync(0xffffffffu, s2, o);
    }
    if (lane == 0) part[w] = s1;
    __syncthreads();
    if (w == 0) {
        float v = part[lane];
#pragma unroll
        for (int o = 16; o; o >>= 1) v += __shfl_xor_sync(0xffffffffu, v, o);
        if (lane == 0) bc[0] = v;
    }
    __syncthreads();
    float n = bc[0];
    g_csn[k] = (ncs + 1e-5f) / (n + 1024.0f * 1e-5f) * n;

    if (lane == 0) part[w] = s2;
    __syncthreads();
    if (k == 0) {
        float ent = 0.0f;
#pragma unroll
        for (int j = 0; j < 32; j++) ent += part[j];
        out[OFF_ENT]  = ent;
        out[OFF_PERP] = expf(ent);
        out[OFF_LOSS] = g_loss * (1.0f / (32768.0f * 256.0f));
    }
}

__global__ void fin2(const float* __restrict__ ea, float* __restrict__ out) {
    int idx = blockIdx.x * 256 + threadIdx.x;
    float v = 0.99f * ea[idx] + 0.01f * g_esum[idx];
    out[OFF_NEA  + idx] = v;
    out[OFF_NEMB + idx] = v / g_csn[idx >> 8];
}

// ---------------------------------------------------------------------------
extern "C" void kernel_launch(void* const* d_in, const int* in_sizes, int n_in,
                              void* d_out, int out_size) {
    const float* z     = (const float*)d_in[0];
    const float* embed = (const float*)d_in[1];
    const float* cs    = (const float*)d_in[2];
    const float* ea    = (const float*)d_in[3];
    float* out = (float*)d_out;

    cudaFuncSetAttribute(vq_gemm, cudaFuncAttributeMaxDynamicSharedMemorySize,
                         SM_TOT);

    e2zc_k<<<256, 256>>>(embed);
    conv_z<<<8192, 256>>>(z);
    vq_gemm<<<dim3(256, 8), 256, SM_TOT>>>();
    vq_epi<<<4096, 256>>>(z, embed, out);
    fin1<<<1, 1024>>>(cs, out);
    fin2<<<1024, 256>>>(ea, out);
}

// round 17
// speedup vs baseline: 1.3800x; 1.0257x over previous
#include <cuda_runtime.h>
#include <cuda_fp16.h>
#include <cstdint>

// Problem constants
#define NTOK 32768
#define KC   1024
#define DD   256
#define KA   512            // stored split length per matrix: [hi | lo]
#define TINV 10.0f

// Output layout (flattened tuple order)
static const long OFF_ZQ    = 0;
static const long OFF_CODES = 8388608;
static const long OFF_LOSS  = 8421376;
static const long OFF_PERP  = 8421377;
static const long OFF_ENT   = 8421378;
static const long OFF_SOFT  = 8421379;   // only 4B-aligned -> scalar access only
static const long OFF_NEMB  = 41975811;
static const long OFF_NCS   = 42237955;
static const long OFF_NEA   = 42238979;

// Device scratch
__device__ float  g_e2[KC];
__device__ float  g_counts[KC];
__device__ float  g_esum[KC * DD];
__device__ float  g_csn[KC];
__device__ float  g_loss;
__device__ __half g_A[(size_t)NTOK * KA];         // [z_hi | z_lo]
__device__ __half g_B[(size_t)KC   * KA];         // [e_hi | e_lo]
__device__ float4 g_dist4[(size_t)NTOK * KC / 4]; // 16B-aligned dist scratch

// ---------------------------------------------------------------------------
__device__ __forceinline__ uint32_t smem_u32(const void* p) {
    uint32_t a;
    asm("{ .reg .u64 t; cvta.to.shared.u64 t, %1; cvt.u32.u64 %0, t; }"
        : "=r"(a) : "l"(p));
    return a;
}
#define SWZ(off) ((off) ^ (((off) >> 3) & 0x70))

__device__ __forceinline__ void cp16(uint32_t s, const void* g) {
    asm volatile("cp.async.cg.shared.global [%0], [%1], 16;"
                 :: "r"(s), "l"(g) : "memory");
}

#define LDSM4(r, addr) \
    asm volatile("ldmatrix.sync.aligned.m8n8.x4.shared.b16 {%0,%1,%2,%3}, [%4];" \
        : "=r"((r)[0]), "=r"((r)[1]), "=r"((r)[2]), "=r"((r)[3]) : "r"(addr))

#define MMA16816(c, a, b) \
    asm volatile("mma.sync.aligned.m16n8k16.row.col.f32.f16.f16.f32 " \
        "{%0,%1,%2,%3}, {%4,%5,%6,%7}, {%8,%9}, {%0,%1,%2,%3};" \
        : "+f"((c)[0]), "+f"((c)[1]), "+f"((c)[2]), "+f"((c)[3]) \
        : "r"((a)[0]), "r"((a)[1]), "r"((a)[2]), "r"((a)[3]), \
          "r"((b)[0]), "r"((b)[1]))

__device__ __forceinline__ void red4(float* a, float4 v) {
    asm volatile("red.global.add.v4.f32 [%0], {%1,%2,%3,%4};"
                 :: "l"(a), "f"(v.x), "f"(v.y), "f"(v.z), "f"(v.w) : "memory");
}

// ---------------------------------------------------------------------------
// Fused: zero scratch + e2[k] + conv of embed into g_B [hi|lo].
__global__ void e2zc_k(const float* __restrict__ embed) {
    int t = blockIdx.x * 256 + threadIdx.x;     // 65536 threads
#pragma unroll
    for (int j = 0; j < 4; j++) g_esum[t * 4 + j] = 0.0f;
    if (t < KC) g_counts[t] = 0.0f;
    if (t == 0) g_loss = 0.0f;

    {
        int n = t >> 6, d4 = (t & 63) * 4;
        float4 v = ((const float4*)embed)[t];
        __half hx = __float2half(v.x), hy = __float2half(v.y);
        __half hz = __float2half(v.z), hw = __float2half(v.w);
        __half lx = __float2half(v.x - __half2float(hx));
        __half ly = __float2half(v.y - __half2float(hy));
        __half lz = __float2half(v.z - __half2float(hz));
        __half lw = __float2half(v.w - __half2float(hw));
        __half* r = g_B + (size_t)n * KA;
        *(__half2*)(r + d4)           = __halves2half2(hx, hy);
        *(__half2*)(r + d4 + 2)       = __halves2half2(hz, hw);
        *(__half2*)(r + 256 + d4)     = __halves2half2(lx, ly);
        *(__half2*)(r + 256 + d4 + 2) = __halves2half2(lz, lw);
    }

    int w = t >> 5, lane = t & 31;
    if (w < KC) {
        const float4* row = (const float4*)(embed + (size_t)w * DD);
        float s = 0.0f;
#pragma unroll
        for (int j = 0; j < 2; j++) {
            float4 v = row[lane + 32 * j];
            s += v.x * v.x + v.y * v.y + v.z * v.z + v.w * v.w;
        }
#pragma unroll
        for (int o = 16; o; o >>= 1) s += __shfl_xor_sync(0xffffffffu, s, o);
        if (lane == 0) g_e2[w] = s;
    }
}

// split f32 -> (hi, lo) f16; layout [hi | lo], row length KA=512
__global__ void conv_z(const float* __restrict__ z) {
    int idx = blockIdx.x * 256 + threadIdx.x;
    int n = idx >> 6, d4 = (idx & 63) * 4;
    float4 v = ((const float4*)z)[idx];
    __half hx = __float2half(v.x), hy = __float2half(v.y);
    __half hz = __float2half(v.z), hw = __float2half(v.w);
    __half lx = __float2half(v.x - __half2float(hx));
    __half ly = __float2half(v.y - __half2float(hy));
    __half lz = __float2half(v.z - __half2float(hz));
    __half lw = __float2half(v.w - __half2float(hw));
    __half* r = g_A + (size_t)n * KA;
    *(__half2*)(r + d4)           = __halves2half2(hx, hy);
    *(__half2*)(r + d4 + 2)       = __halves2half2(hz, hw);
    *(__half2*)(r + 256 + d4)     = __halves2half2(lx, ly);
    *(__half2*)(r + 256 + d4 + 2) = __halves2half2(lz, lw);
}

// ---------------------------------------------------------------------------
// HMMA GEMM (frozen geometry): CTA = 128 tokens x 128 codes, 8 warps as
// 4(m) x 2(n), warp tile 32x64, 3-stage cp.async pipeline, 2 CTAs/SM.
// Logical K=768 as 12 chunks of 64 remapped into [hi|lo] K=512 buffers:
//   c 0-3: A hi x B hi; c 4-7: A lo x B hi; c 8-11: A hi x B lo.
// Writes dist = e2 - 2*dot into g_dist (aligned scratch) with float2 stores.
#define SM_STG 32768     // per stage: A 16KB + B 16KB
#define SM_TOT (3 * SM_STG)
#define NCH    12

__device__ __forceinline__ void load_chunk(uint32_t sb, const char* Ag,
                                           const char* Bg, int c, int stg,
                                           int tid) {
    int ac = (c < 8) ? c : c - 8;
    int bc = (c < 4) ? c : c - 4;
    uint32_t base = sb + stg * SM_STG;
#pragma unroll
    for (int q = 0; q < 4; q++) {              // A: 128 rows x 128B
        int i = tid + 256 * q, r = i >> 3, j = i & 7;
        uint32_t off = (uint32_t)(r * 128 + j * 16);
        cp16(base + SWZ(off), Ag + (size_t)r * (KA * 2) + ac * 128 + j * 16);
    }
#pragma unroll
    for (int q = 0; q < 4; q++) {              // B: 128 rows x 128B
        int i = tid + 256 * q, r = i >> 3, j = i & 7;
        uint32_t off = (uint32_t)(r * 128 + j * 16);
        cp16(base + 16384 + SWZ(off), Bg + (size_t)r * (KA * 2) + bc * 128 + j * 16);
    }
    asm volatile("cp.async.commit_group;" ::: "memory");
}

extern __shared__ char gsm[];

__global__ __launch_bounds__(256, 2)
void vq_gemm() {
    __shared__ float e2t[128];
    uint32_t sb = smem_u32(gsm);
    int tid = threadIdx.x, lane = tid & 31, wid = tid >> 5;
    int row0 = blockIdx.x * 128, col0 = blockIdx.y * 128;
    int wm = (wid & 3) * 32, wn = (wid >> 2) * 64;

    if (tid < 128) e2t[tid] = g_e2[col0 + tid];

    const char* Ag = (const char*)g_A + (size_t)row0 * (KA * 2);
    const char* Bg = (const char*)g_B + (size_t)col0 * (KA * 2);

    float acc[2][8][4] = {};

    load_chunk(sb, Ag, Bg, 0, 0, tid);
    load_chunk(sb, Ag, Bg, 1, 1, tid);

    int stg = 0, lstg = 2;
    for (int c = 0; c < NCH; c++) {
        if (c < NCH - 1) asm volatile("cp.async.wait_group 1;" ::: "memory");
        else             asm volatile("cp.async.wait_group 0;" ::: "memory");
        __syncthreads();
        if (c + 2 < NCH) load_chunk(sb, Ag, Bg, c + 2, lstg, tid);

        uint32_t sa = sb + stg * SM_STG;
        uint32_t sB = sa + 16384;
#pragma unroll
        for (int ks = 0; ks < 4; ks++) {
            uint32_t a[2][4];
#pragma unroll
            for (int mt = 0; mt < 2; mt++) {
                uint32_t off = (uint32_t)((wm + mt * 16 + (lane & 15)) * 128
                                          + ks * 32 + (lane >> 4) * 16);
                LDSM4(a[mt], sa + SWZ(off));
            }
            uint32_t b[8][2];
#pragma unroll
            for (int p = 0; p < 4; p++) {
                uint32_t r4[4];
                uint32_t off = (uint32_t)((wn + p * 16 + (lane & 7)
                                           + ((lane >> 4) << 3)) * 128
                                          + ks * 32 + ((lane >> 3) & 1) * 16);
                LDSM4(r4, sB + SWZ(off));
                b[2 * p][0] = r4[0];     b[2 * p][1] = r4[1];
                b[2 * p + 1][0] = r4[2]; b[2 * p + 1][1] = r4[3];
            }
#pragma unroll
            for (int mt = 0; mt < 2; mt++)
#pragma unroll
                for (int nt = 0; nt < 8; nt++)
                    MMA16816(acc[mt][nt], a[mt], b[nt]);
        }
        stg  = (stg  == 2) ? 0 : stg + 1;
        lstg = (lstg == 2) ? 0 : lstg + 1;
    }

    // Epilogue: dist = e2 - 2*dot into aligned scratch, float2 stores.
    float* gd = (float*)g_dist4;
#pragma unroll
    for (int mt = 0; mt < 2; mt++) {
#pragma unroll
        for (int nt = 0; nt < 8; nt++) {
            int r  = row0 + wm + mt * 16 + (lane >> 2);
            int lc = wn + nt * 8 + (lane & 3) * 2;
            float* d0 = gd + (size_t)r * KC + col0 + lc;
            float2 v0, v1;
            v0.x = e2t[lc]     - 2.0f * acc[mt][nt][0];
            v0.y = e2t[lc + 1] - 2.0f * acc[mt][nt][1];
            v1.x = e2t[lc]     - 2.0f * acc[mt][nt][2];
            v1.y = e2t[lc + 1] - 2.0f * acc[mt][nt][3];
            *(float2*)d0            = v0;
            *(float2*)(d0 + 8 * KC) = v1;
        }
    }
}

// ---------------------------------------------------------------------------
// Per-row epilogue (round-8 addressing): one warp per row, 8 rows per CTA.
// Lane owns codes {j*32+lane} -> scalar dist loads AND soft stores are both
// fully coalesced (128B/warp per instruction).
__global__ __launch_bounds__(256)
void vq_epi(const float* __restrict__ z,
            const float* __restrict__ embed,
            float* __restrict__ out) {
    int tid = threadIdx.x, lane = tid & 31, w = tid >> 5;
    int row = blockIdx.x * 8 + w;
    const float* dist = (const float*)g_dist4 + (size_t)row * KC;

    float dv[32];
    float mn = 3.4e38f; int arg = 0;
#pragma unroll
    for (int j = 0; j < 32; j++) {
        int k = j * 32 + lane;
        float d = dist[k];
        dv[j] = d;
        if (d < mn) { mn = d; arg = k; }
    }
#pragma unroll
    for (int o = 16; o; o >>= 1) {
        float ov = __shfl_xor_sync(0xffffffffu, mn, o);
        int   oa = __shfl_xor_sync(0xffffffffu, arg, o);
        if (ov < mn || (ov == mn && oa < arg)) { mn = ov; arg = oa; }
    }

    float sum = 0.0f;
#pragma unroll
    for (int j = 0; j < 32; j++) {
        float v = __expf((mn - dv[j]) * TINV);
        dv[j] = v;
        sum += v;
    }
#pragma unroll
    for (int o = 16; o; o >>= 1) sum += __shfl_xor_sync(0xffffffffu, sum, o);
    float inv = 1.0f / sum;

    float* soft = out + OFF_SOFT + (size_t)row * KC;
#pragma unroll
    for (int j = 0; j < 32; j++)
        soft[j * 32 + lane] = dv[j] * inv;

    // z_q, loss, EMA — vectorized float4 + v4 reductions
    int code = arg;
    const float4* er4 = (const float4*)(embed + (size_t)code * DD);
    const float4* zr4 = (const float4*)(z     + (size_t)row  * DD);
    float4*       zq4 = (float4*)(out + OFF_ZQ + (size_t)row * DD);
    float lp = 0.0f;
#pragma unroll
    for (int j = 0; j < 2; j++) {
        int i = lane * 2 + j;                  // float4 index 0..63
        float4 ev = er4[i], zv = zr4[i];
        zq4[i] = ev;
        float dx = zv.x - ev.x, dy = zv.y - ev.y;
        float dz = zv.z - ev.z, dw = zv.w - ev.w;
        lp += dx * dx + dy * dy + dz * dz + dw * dw;
        red4(g_esum + code * DD + i * 4, zv);
    }
#pragma unroll
    for (int o = 16; o; o >>= 1) lp += __shfl_xor_sync(0xffffffffu, lp, o);
    if (lane == 0) {
        out[OFF_CODES + row] = (float)code;
        atomicAdd(&g_counts[code], 1.0f);
        atomicAdd(&g_loss, lp);
    }
}

// ---------------------------------------------------------------------------
__global__ void fin1(const float* __restrict__ cs, float* __restrict__ out) {
    __shared__ float part[32];
    __shared__ float bc[2];
    int k = threadIdx.x, lane = k & 31, w = k >> 5;

    float cnt = g_counts[k];
    float ncs = 0.99f * cs[k] + 0.01f * cnt;
    out[OFF_NCS + k] = ncs;

    float p = cnt * (1.0f / 32768.0f);
    float s1 = ncs;
    float s2 = -p * logf(p + 1e-10f);
#pragma unroll
    for (int o = 16; o; o >>= 1) {
        s1 += __shfl_xor_sync(0xffffffffu, s1, o);
        s2 += __shfl_xor_sync(0xffffffffu, s2, o);
    }
    if (lane == 0) part[w] = s1;
    __syncthreads();
    if (w == 0) {
        float v = part[lane];
#pragma unroll
        for (int o = 16; o; o >>= 1) v += __shfl_xor_sync(0xffffffffu, v, o);
        if (lane == 0) bc[0] = v;
    }
    __syncthreads();
    float n = bc[0];
    g_csn[k] = (ncs + 1e-5f) / (n + 1024.0f * 1e-5f) * n;

    if (lane == 0) part[w] = s2;
    __syncthreads();
    if (k == 0) {
        float ent = 0.0f;
#pragma unroll
        for (int j = 0; j < 32; j++) ent += part[j];
        out[OFF_ENT]  = ent;
        out[OFF_PERP] = expf(ent);
        out[OFF_LOSS] = g_loss * (1.0f / (32768.0f * 256.0f));
    }
}

__global__ void fin2(const float* __restrict__ ea, float* __restrict__ out) {
    int idx = blockIdx.x * 256 + threadIdx.x;
    float v = 0.99f * ea[idx] + 0.01f * g_esum[idx];
    out[OFF_NEA  + idx] = v;
    out[OFF_NEMB + idx] = v / g_csn[idx >> 8];
}

// ---------------------------------------------------------------------------
extern "C" void kernel_launch(void* const* d_in, const int* in_sizes, int n_in,
                              void* d_out, int out_size) {
    const float* z     = (const float*)d_in[0];
    const float* embed = (const float*)d_in[1];
    const float* cs    = (const float*)d_in[2];
    const float* ea    = (const float*)d_in[3];
    float* out = (float*)d_out;

    cudaFuncSetAttribute(vq_gemm, cudaFuncAttributeMaxDynamicSharedMemorySize,
                         SM_TOT);

    e2zc_k<<<256, 256>>>(embed);
    conv_z<<<8192, 256>>>(z);
    vq_gemm<<<dim3(256, 8), 256, SM_TOT>>>();
    vq_epi<<<4096, 256>>>(z, embed, out);
    fin1<<<1, 1024>>>(cs, out);
    fin2<<<1024, 256>>>(ea, out);
}